// round 13
// baseline (speedup 1.0000x reference)
#include <cuda_runtime.h>
#include <math_constants.h>

// B=4, N=M=4096, D=3; scalar fp32 output
#define BATCH   4
#define NP      4096
#define G       16
#define NC      (G * G * G)          // 4096 cells per cloud
#define CW      1.0f                 // cell width
#define ORG     (-8.0f)              // grid origin (covers all N(0,1) samples)
#define NCLOUD  8                    // [arr(0=X,1=Y)][b] -> arr*BATCH+b

// Query kernel geometry
#define QBLK    1024                 // 1-warp blocks
#define QTPB    32

__device__ unsigned g_count[NCLOUD * NC];        // histogram; zeroed by query kernel for next replay
__device__ unsigned g_start[NCLOUD * (NC + 1)];  // exclusive prefix (rewritten every run)
__device__ unsigned g_cursor[NCLOUD * NC];       // scatter cursors (rewritten every run)
__device__ float4   g_pts[NCLOUD * NP];          // cell-sorted points
__device__ float    g_bsum[QBLK];
__device__ unsigned g_done;                      // zero-init; self-resetting

__device__ __forceinline__ int cell_of(float qx, float qy, float qz,
                                       int& cx, int& cy, int& cz) {
    cx = min(max((int)floorf(qx - ORG), 0), G - 1);
    cy = min(max((int)floorf(qy - ORG), 0), G - 1);
    cz = min(max((int)floorf(qz - ORG), 0), G - 1);
    return (cz * G + cy) * G + cx;
}

// ---- Kernel 1: per-cell histogram --------------------------------------------
__global__ __launch_bounds__(256)
void k_hist(const float* __restrict__ X, const float* __restrict__ Y) {
    const int idx = blockIdx.x * 256 + threadIdx.x;      // 0..32767
    const int arr = idx >> 14;
    const int b   = (idx >> 12) & 3;
    const int i   = idx & 4095;
    const float* P = arr ? Y : X;
    const float* p = P + ((size_t)b * NP + i) * 3;
    int cx, cy, cz;
    const int cell = cell_of(p[0], p[1], p[2], cx, cy, cz);
    atomicAdd(&g_count[(arr * BATCH + b) * NC + cell], 1u);
}

// ---- Kernel 2: exclusive scan per cloud (one block each) ---------------------
__global__ __launch_bounds__(1024)
void k_scan() {
    const int cid = blockIdx.x;
    const unsigned* cnt = g_count + cid * NC;
    unsigned* st  = g_start + cid * (NC + 1);
    unsigned* cur = g_cursor + cid * NC;
    const int t = threadIdx.x, lane = t & 31, wid = t >> 5;

    const int b4 = t * 4;
    unsigned v0 = cnt[b4], v1 = cnt[b4 + 1], v2 = cnt[b4 + 2], v3 = cnt[b4 + 3];
    unsigned tsum = v0 + v1 + v2 + v3;

    unsigned inc = tsum;
    #pragma unroll
    for (int o = 1; o < 32; o <<= 1) {
        unsigned n = __shfl_up_sync(0xFFFFFFFFu, inc, o);
        if (lane >= o) inc += n;
    }
    __shared__ unsigned ws[32];
    if (lane == 31) ws[wid] = inc;
    __syncthreads();
    if (wid == 0) {
        unsigned wv = ws[lane];
        unsigned winc = wv;
        #pragma unroll
        for (int o = 1; o < 32; o <<= 1) {
            unsigned n = __shfl_up_sync(0xFFFFFFFFu, winc, o);
            if (lane >= o) winc += n;
        }
        ws[lane] = winc - wv;     // exclusive warp offsets
    }
    __syncthreads();

    unsigned s = ws[wid] + inc - tsum;
    st[b4] = s;     cur[b4] = s;     s += v0;
    st[b4 + 1] = s; cur[b4 + 1] = s; s += v1;
    st[b4 + 2] = s; cur[b4 + 2] = s; s += v2;
    st[b4 + 3] = s; cur[b4 + 3] = s; s += v3;
    if (t == 1023) st[NC] = s;
}

// ---- Kernel 3: scatter points into cell-sorted order -------------------------
__global__ __launch_bounds__(256)
void k_scatter(const float* __restrict__ X, const float* __restrict__ Y) {
    const int idx = blockIdx.x * 256 + threadIdx.x;
    const int arr = idx >> 14;
    const int b   = (idx >> 12) & 3;
    const int i   = idx & 4095;
    const float* P = arr ? Y : X;
    const float* p = P + ((size_t)b * NP + i) * 3;
    const float px = p[0], py = p[1], pz = p[2];
    int cx, cy, cz;
    const int cell = cell_of(px, py, pz, cx, cy, cz);
    const int cid = arr * BATCH + b;
    const unsigned pos = atomicAdd(&g_cursor[cid * NC + cell], 1u);
    g_pts[cid * NP + pos] = make_float4(px, py, pz, 0.0f);
}

// ---- Kernel 4: NN query + reduction + cleanup --------------------------------
__global__ __launch_bounds__(QTPB)
void k_query(const float* __restrict__ X, const float* __restrict__ Y,
             float* __restrict__ out) {
    const int idx = blockIdx.x * QTPB + threadIdx.x;     // 0..32767 (original index order)
    const int dir = idx >> 14;                           // blocks [0,512)=dir0, [512,1024)=dir1
    const int b   = (idx >> 12) & 3;
    const int i   = idx & 4095;

    const float* Qa = dir ? Y : X;
    const int tcid = (dir ? 0 : 1) * BATCH + b;          // target cloud's grid
    const float* qp = Qa + ((size_t)b * NP + i) * 3;
    const float qx = qp[0], qy = qp[1], qz = qp[2];
    int cx, cy, cz;
    cell_of(qx, qy, qz, cx, cy, cz);

    const unsigned* __restrict__ st = g_start + tcid * (NC + 1);
    const float4*   __restrict__ pts = g_pts + tcid * NP;

    float best = CUDART_INF_F;

    // Rings 0-1: 3x3x3 neighborhood as 9 contiguous x-row spans
    #pragma unroll
    for (int dz = -1; dz <= 1; dz++) {
        const int z = cz + dz;
        if ((unsigned)z >= G) continue;
        #pragma unroll
        for (int dy = -1; dy <= 1; dy++) {
            const int y = cy + dy;
            if ((unsigned)y >= G) continue;
            const int rowb = (z * G + y) * G;
            const int x0 = max(cx - 1, 0), x1 = min(cx + 1, G - 1);
            const unsigned s0 = st[rowb + x0];
            const unsigned e0 = st[rowb + x1 + 1];
            for (unsigned u = s0; u < e0; u++) {
                const float4 t = pts[u];
                const float dx = qx - t.x, dyf = qy - t.y, dzf = qz - t.z;
                const float d2 = fmaf(dx, dx, fmaf(dyf, dyf, dzf * dzf));
                best = fminf(best, d2);
            }
        }
    }

    // Rare far rings, exact bound: points in ring >= k+1 have d >= k*CW
    float bmin = CW * CW;
    for (int k = 2; k < G && best > bmin; k++) {
        for (int dz = -k; dz <= k; dz++) {
            const int z = cz + dz;
            if ((unsigned)z >= G) continue;
            const bool zface = (dz == -k) || (dz == k);
            for (int dy = -k; dy <= k; dy++) {
                const int y = cy + dy;
                if ((unsigned)y >= G) continue;
                const int rowb = (z * G + y) * G;
                if (zface || dy == -k || dy == k) {
                    const int x0 = max(cx - k, 0), x1 = min(cx + k, G - 1);
                    const unsigned s0 = st[rowb + x0];
                    const unsigned e0 = st[rowb + x1 + 1];
                    for (unsigned u = s0; u < e0; u++) {
                        const float4 t = pts[u];
                        const float dx = qx - t.x, dyf = qy - t.y, dzf = qz - t.z;
                        best = fminf(best, fmaf(dx, dx, fmaf(dyf, dyf, dzf * dzf)));
                    }
                } else {
                    const int xa = cx - k, xb = cx + k;
                    if (xa >= 0) {
                        const unsigned s0 = st[rowb + xa], e0 = st[rowb + xa + 1];
                        for (unsigned u = s0; u < e0; u++) {
                            const float4 t = pts[u];
                            const float dx = qx - t.x, dyf = qy - t.y, dzf = qz - t.z;
                            best = fminf(best, fmaf(dx, dx, fmaf(dyf, dyf, dzf * dzf)));
                        }
                    }
                    if (xb < G) {
                        const unsigned s0 = st[rowb + xb], e0 = st[rowb + xb + 1];
                        for (unsigned u = s0; u < e0; u++) {
                            const float4 t = pts[u];
                            const float dx = qx - t.x, dyf = qy - t.y, dzf = qz - t.z;
                            best = fminf(best, fmaf(dx, dx, fmaf(dyf, dyf, dzf * dzf)));
                        }
                    }
                }
            }
        }
        bmin = ((float)k * CW) * ((float)k * CW);
    }

    // Warp-sum (block == 1 warp), deterministic membership (original indices)
    float lsum = best;
    #pragma unroll
    for (int o = 16; o > 0; o >>= 1)
        lsum += __shfl_xor_sync(0xFFFFFFFFu, lsum, o);
    if (threadIdx.x == 0) g_bsum[blockIdx.x] = lsum;

    // Zero histogram slice for next graph replay (not read again this run)
    g_count[blockIdx.x * (NCLOUD * NC / QBLK) + threadIdx.x * 0 + (threadIdx.x)] = 0u;
    // (NCLOUD*NC/QBLK == 32 == QTPB: each thread zeroes exactly one counter)

    unsigned tk = 0xFFFFFFFFu;
    if (threadIdx.x == 0) {
        __threadfence();
        tk = atomicAdd(&g_done, 1u);
    }
    tk = __shfl_sync(0xFFFFFFFFu, tk, 0);
    if (tk != QBLK - 1) return;
    __threadfence();   // acquire: all block sums visible

    // Final reduction: bsum[0:512)=dir0, [512:1024)=dir1
    float s0 = 0.0f, s1 = 0.0f;
    #pragma unroll
    for (int j = 0; j < 16; j++) {
        s0 += __ldcg(&g_bsum[threadIdx.x + j * 32]);
        s1 += __ldcg(&g_bsum[512 + threadIdx.x + j * 32]);
    }
    #pragma unroll
    for (int o = 16; o > 0; o >>= 1) {
        s0 += __shfl_xor_sync(0xFFFFFFFFu, s0, o);
        s1 += __shfl_xor_sync(0xFFFFFFFFu, s1, o);
    }
    if (threadIdx.x == 0) {
        out[0] = fmaxf(s0, s1) * (1.0f / (float)(BATCH * NP));
        g_done = 0u;    // reset for next replay
    }
}

extern "C" void kernel_launch(void* const* d_in, const int* in_sizes, int n_in,
                              void* d_out, int out_size) {
    const float* x = (const float*)d_in[0];
    const float* y = (const float*)d_in[1];
    float* out = (float*)d_out;

    k_hist<<<128, 256>>>(x, y);
    k_scan<<<NCLOUD, 1024>>>();
    k_scatter<<<128, 256>>>(x, y);
    k_query<<<QBLK, QTPB>>>(x, y, out);
}

// round 14
// speedup vs baseline: 1.1828x; 1.1828x over previous
#include <cuda_runtime.h>
#include <math_constants.h>

// B=4, N=M=4096, D=3; scalar fp32 output
#define BATCH   4
#define NP      4096
#define G       16
#define NC      (G * G * G)          // 4096 cells per cloud
#define CW      1.0f
#define ORG     (-8.0f)              // covers all N(0,1) samples
#define NCLOUD  8                    // [arr(0=X,1=Y)][b] -> arr*4+b

#define ABLK    128                  // build kernel: fully co-resident grid
#define ATPB    256
#define QBLK    256                  // query kernel
#define QTPB    256

__device__ unsigned g_count[NCLOUD * NC];        // zeroed at build start each run
__device__ unsigned g_start[NCLOUD * (NC + 1)];
__device__ unsigned g_cursor[NCLOUD * NC];
__device__ float4   g_pts[NCLOUD * NP];          // cell-sorted points
__device__ float    g_bsum[QBLK];
__device__ unsigned g_sync[3];                   // build grid-syncs; reset by query kernel
__device__ unsigned g_done;                      // reset by query kernel

__device__ __forceinline__ void cell_of(float qx, float qy, float qz,
                                        int& cx, int& cy, int& cz) {
    cx = min(max((int)floorf(qx - ORG), 0), G - 1);
    cy = min(max((int)floorf(qy - ORG), 0), G - 1);
    cz = min(max((int)floorf(qz - ORG), 0), G - 1);
}

__device__ __forceinline__ void gridsync(int s) {
    __syncthreads();
    if (threadIdx.x == 0) {
        __threadfence();
        atomicAdd(&g_sync[s], 1u);
        while (*(volatile unsigned*)&g_sync[s] < ABLK) __nanosleep(32);
    }
    __syncthreads();
    __threadfence();   // acquire
}

// ---- Kernel 1: fused zero + hist + scan + scatter (grid-wide syncs) ----------
__global__ __launch_bounds__(ATPB)
void k_build(const float* __restrict__ X, const float* __restrict__ Y) {
    const int t = blockIdx.x * ATPB + threadIdx.x;       // 0..32767

    // Phase 0: zero histogram (one counter per thread)
    g_count[t] = 0u;
    gridsync(0);

    // Phase 1: histogram (point stays in registers for phase 3)
    const int arr = t >> 14, b = (t >> 12) & 3, i = t & 4095;
    const float* P = arr ? Y : X;
    const float* p = P + ((size_t)b * NP + i) * 3;
    const float px = p[0], py = p[1], pz = p[2];
    int cx, cy, cz;
    cell_of(px, py, pz, cx, cy, cz);
    const int cell = (cz * G + cy) * G + cx;
    const int cid  = arr * BATCH + b;
    atomicAdd(&g_count[cid * NC + cell], 1u);
    gridsync(1);

    // Phase 2: exclusive scan, one cloud per block (blocks 0..7), 16 cells/thread
    if (blockIdx.x < NCLOUD) {
        const int scid = blockIdx.x;
        const unsigned* cnt = g_count + scid * NC;
        unsigned* st  = g_start + scid * (NC + 1);
        unsigned* cur = g_cursor + scid * NC;
        const int tt = threadIdx.x, lane = tt & 31, wid = tt >> 5;
        const int base = tt * 16;
        unsigned v[16], tsum = 0;
        #pragma unroll
        for (int j = 0; j < 16; j++) { v[j] = cnt[base + j]; tsum += v[j]; }
        unsigned inc = tsum;
        #pragma unroll
        for (int o = 1; o < 32; o <<= 1) {
            unsigned n = __shfl_up_sync(0xFFFFFFFFu, inc, o);
            if (lane >= o) inc += n;
        }
        __shared__ unsigned ws[8];
        if (lane == 31) ws[wid] = inc;
        __syncthreads();
        if (wid == 0) {
            unsigned wv = (lane < 8) ? ws[lane] : 0u;
            unsigned winc = wv;
            #pragma unroll
            for (int o = 1; o < 8; o <<= 1) {
                unsigned n = __shfl_up_sync(0xFFFFFFFFu, winc, o);
                if (lane >= o) winc += n;
            }
            if (lane < 8) ws[lane] = winc - wv;
        }
        __syncthreads();
        unsigned s = ws[wid] + inc - tsum;
        #pragma unroll
        for (int j = 0; j < 16; j++) { st[base + j] = s; cur[base + j] = s; s += v[j]; }
        if (tt == ATPB - 1) st[NC] = s;
    }
    gridsync(2);

    // Phase 3: scatter
    const unsigned pos = atomicAdd(&g_cursor[cid * NC + cell], 1u);
    g_pts[cid * NP + pos] = make_float4(px, py, pz, 0.0f);
}

// ---- Kernel 2: NN query in cell-sorted order, 2 lanes per query --------------
__global__ __launch_bounds__(QTPB)
void k_query(float* __restrict__ out) {
    const int t = blockIdx.x * QTPB + threadIdx.x;       // 0..65535
    const int qidx = t >> 1;                             // sorted-order query id
    const int pr   = t & 1;                              // row-parity split
    const int qcid = qidx >> 12;                         // 0..7 (0-3: X/dir0, 4-7: Y/dir1)
    const int i    = qidx & 4095;
    const int tcid = qcid ^ 4;                           // opposite cloud, same batch

    const float4 q = g_pts[qcid * NP + i];
    const float qx = q.x, qy = q.y, qz = q.z;
    int cx, cy, cz;
    cell_of(qx, qy, qz, cx, cy, cz);

    const unsigned* __restrict__ st  = g_start + tcid * (NC + 1);
    const float4*   __restrict__ pts = g_pts + tcid * NP;

    // Prefetch this lane's row spans (rows pr, pr+2, ... of the 9 = 3x3 (dz,dy) rows)
    unsigned ss[5], ee[5];
    #pragma unroll
    for (int k = 0; k < 5; k++) {
        const int r = pr + 2 * k;
        unsigned s = 0, e = 0;
        if (r < 9) {
            const int dz = r / 3 - 1, dy = r % 3 - 1;
            const int z = cz + dz, y = cy + dy;
            if ((unsigned)z < G && (unsigned)y < G) {
                const int rowb = (z * G + y) * G;
                const int x0 = max(cx - 1, 0), x1 = min(cx + 1, G - 1);
                s = st[rowb + x0];
                e = st[rowb + x1 + 1];
            }
        }
        ss[k] = s; ee[k] = e;
    }

    float best = CUDART_INF_F;
    #pragma unroll
    for (int k = 0; k < 5; k++) {
        for (unsigned u = ss[k]; u < ee[k]; u++) {
            const float4 tp = pts[u];
            const float dx = qx - tp.x, dy = qy - tp.y, dz = qz - tp.z;
            best = fminf(best, fmaf(dx, dx, fmaf(dy, dy, dz * dz)));
        }
    }
    // Combine the two lanes of this query
    best = fminf(best, __shfl_xor_sync(0xFFFFFFFFu, best, 1));

    // Rare far rings (exact bound: unscanned ring >= k+1 is at distance >= k*CW)
    if (pr == 0 && best > CW * CW) {
        float bmin = CW * CW;
        for (int k = 2; k < G && best > bmin; k++) {
            for (int dz = -k; dz <= k; dz++) {
                const int z = cz + dz;
                if ((unsigned)z >= G) continue;
                const bool zface = (dz == -k) || (dz == k);
                for (int dy = -k; dy <= k; dy++) {
                    const int y = cy + dy;
                    if ((unsigned)y >= G) continue;
                    const int rowb = (z * G + y) * G;
                    if (zface || dy == -k || dy == k) {
                        const int x0 = max(cx - k, 0), x1 = min(cx + k, G - 1);
                        for (unsigned u = st[rowb + x0]; u < st[rowb + x1 + 1]; u++) {
                            const float4 tp = pts[u];
                            const float dx = qx - tp.x, dyf = qy - tp.y, dzf = qz - tp.z;
                            best = fminf(best, fmaf(dx, dx, fmaf(dyf, dyf, dzf * dzf)));
                        }
                    } else {
                        const int xa = cx - k, xb = cx + k;
                        if (xa >= 0)
                            for (unsigned u = st[rowb + xa]; u < st[rowb + xa + 1]; u++) {
                                const float4 tp = pts[u];
                                const float dx = qx - tp.x, dyf = qy - tp.y, dzf = qz - tp.z;
                                best = fminf(best, fmaf(dx, dx, fmaf(dyf, dyf, dzf * dzf)));
                            }
                        if (xb < G)
                            for (unsigned u = st[rowb + xb]; u < st[rowb + xb + 1]; u++) {
                                const float4 tp = pts[u];
                                const float dx = qx - tp.x, dyf = qy - tp.y, dzf = qz - tp.z;
                                best = fminf(best, fmaf(dx, dx, fmaf(dyf, dyf, dzf * dzf)));
                            }
                    }
                }
            }
            bmin = ((float)k * CW) * ((float)k * CW);
        }
    }

    // Block sum (even lanes carry the query's d2)
    float lsum = (pr == 0) ? best : 0.0f;
    #pragma unroll
    for (int o = 16; o > 0; o >>= 1)
        lsum += __shfl_xor_sync(0xFFFFFFFFu, lsum, o);
    __shared__ float wsum[QTPB / 32];
    const int wid = threadIdx.x >> 5, lane = threadIdx.x & 31;
    if (lane == 0) wsum[wid] = lsum;
    __syncthreads();

    __shared__ unsigned gtk;
    if (threadIdx.x == 0) {
        float ssum = 0.0f;
        #pragma unroll
        for (int w = 0; w < QTPB / 32; w++) ssum += wsum[w];
        g_bsum[blockIdx.x] = ssum;
        __threadfence();
        gtk = atomicAdd(&g_done, 1u);
    }
    __syncthreads();
    if (gtk != QBLK - 1) return;
    __threadfence();   // acquire: all block sums visible

    // Final: bsum[0:128)=dir0, [128:256)=dir1
    float s0 = 0.0f, s1 = 0.0f;
    if (threadIdx.x < 128) {
        s0 = __ldcg(&g_bsum[threadIdx.x]);
        s1 = __ldcg(&g_bsum[128 + threadIdx.x]);
    }
    #pragma unroll
    for (int o = 16; o > 0; o >>= 1) {
        s0 += __shfl_xor_sync(0xFFFFFFFFu, s0, o);
        s1 += __shfl_xor_sync(0xFFFFFFFFu, s1, o);
    }
    __shared__ float f0[QTPB / 32], f1[QTPB / 32];
    if (lane == 0) { f0[wid] = s0; f1[wid] = s1; }
    __syncthreads();
    if (threadIdx.x == 0) {
        float a0 = 0.0f, a1 = 0.0f;
        #pragma unroll
        for (int w = 0; w < 4; w++) { a0 += f0[w]; a1 += f1[w]; }   // warps 0-3 hold data
        out[0] = fmaxf(a0, a1) * (1.0f / (float)(BATCH * NP));
        g_sync[0] = 0u; g_sync[1] = 0u; g_sync[2] = 0u;            // reset for next replay
        g_done = 0u;
    }
}

extern "C" void kernel_launch(void* const* d_in, const int* in_sizes, int n_in,
                              void* d_out, int out_size) {
    const float* x = (const float*)d_in[0];
    const float* y = (const float*)d_in[1];
    float* out = (float*)d_out;

    k_build<<<ABLK, ATPB>>>(x, y);
    k_query<<<QBLK, QTPB>>>(out);
}